// round 16
// baseline (speedup 1.0000x reference)
#include <cuda_runtime.h>
#include <cuda_bf16.h>

#define BB 8
#define FF 128
#define PP 256
#define TT 2048

__device__ __forceinline__ float ex2f(float x) {
    float r;
    asm("ex2.approx.f32 %0, %1;" : "=f"(r) : "f"(x));
    return r;
}

// warp-autonomous: warp owns 64 ticks x 16 pe-channels as TWO 32-tick
// sub-tiles fused in one flash loop (one shfl + one LDG stream per flash,
// two independent ex2/FMA chains -> ILP-2). No smem, no barriers.
__global__ __launch_bounds__(128, 7)
void flash_reco_kernel(const float* __restrict__ pe,     // [B,F,P]
                       const float* __restrict__ ftime,  // [B,F]
                       const float* __restrict__ conf,   // [B,F]
                       const float* __restrict__ sigma_ptr,
                       float* __restrict__ out)          // [B,P,T]
{
    const int lane = threadIdx.x & 31;
    const int warp = threadIdx.x >> 5;
    const int b    = blockIdx.z;
    const int p0   = blockIdx.y * 16;                    // warp's 16 p
    const int t0   = blockIdx.x * 256 + warp * 64;       // warp's 64 ticks

    const float* __restrict__ base = pe + (size_t)(b * FF) * PP + p0;

    // cooperative prefetch: warm all 128 rows' 64B segment at this p0
    // (the 64B-aligned segment sits in one 128B line -> 1 prefetch per row).
    asm volatile("prefetch.global.L1 [%0];"
                 :: "l"(base + (warp * 32 + lane) * PP));

    const float sigma = sigma_ptr ? __ldg(sigma_ptr) : 1.0f;
    const float inv_s = 1.0f / sigma;
    const float W     = 6.0f * sigma;             // exp(-18) ~ 1.5e-8: negligible
    // interior normalizer: sigma*sqrt(2*pi); theta correction < 2.7e-9 @ sigma>=0.9
    const float inv_anorm = 1.0f / (sigma * 2.5066282746310002f + 1e-10f);
    const bool  analytic_ok = (sigma >= 0.9f);
    const float c2 = -0.72134752044448170f * inv_s * inv_s;  // -log2(e)/2 / s^2

    // ---- prefix: lane owns f = 4*lane+j; tb and lc = log2(conf/anorm) ----
    float4 tb4 = __ldg(reinterpret_cast<const float4*>(ftime + b * FF) + lane);
    float4 cf4 = __ldg(reinterpret_cast<const float4*>(conf  + b * FF) + lane);
    float tbs[4], lcs[4];
    tbs[0] = fminf(fmaxf(tb4.x * (float)TT, 0.0f), (float)(TT - 1));
    tbs[1] = fminf(fmaxf(tb4.y * (float)TT, 0.0f), (float)(TT - 1));
    tbs[2] = fminf(fmaxf(tb4.z * (float)TT, 0.0f), (float)(TT - 1));
    tbs[3] = fminf(fmaxf(tb4.w * (float)TT, 0.0f), (float)(TT - 1));
    lcs[0] = __log2f(cf4.x * inv_anorm);          // conf>=0: log2(0)=-inf -> w=0 ok
    lcs[1] = __log2f(cf4.y * inv_anorm);
    lcs[2] = __log2f(cf4.z * inv_anorm);
    lcs[3] = __log2f(cf4.w * inv_anorm);

    const float t_f = (float)(t0 + lane);                // sub0 tick; sub1 = +32
    const float wlo = (float)t0 - W;                     // union window
    const float whi = (float)(t0 + 63) + W;
    const float elo = W, ehi = (float)(TT - 1) - W;

    unsigned long long acc0[8], acc1[8];                 // 2 x 8 packed f32x2
    #pragma unroll
    for (int j = 0; j < 8; ++j) { acc0[j] = 0ull; acc1[j] = 0ull; }

    #pragma unroll
    for (int j = 0; j < 4; ++j) {
        unsigned mask =
            __ballot_sync(0xffffffffu, tbs[j] >= wlo && tbs[j] <= whi);
        while (mask) {                            // ascending f: deterministic
            const int k = __ffs(mask) - 1;
            mask &= mask - 1;
            const float tbk = __shfl_sync(0xffffffffu, tbs[j], k);
            float lc = __shfl_sync(0xffffffffu, lcs[j], k);

            if (!(analytic_ok && tbk >= elo && tbk <= ehi)) {  // rare, uniform
                const int lo = max(0, (int)ceilf(tbk - W));
                const int hi = min(TT - 1, (int)floorf(tbk + W));
                float s = 0.0f;
                for (int t = lo + lane; t <= hi; t += 32) {
                    const float zz = ((float)t - tbk) * inv_s;
                    s += __expf(-0.5f * zz * zz);
                }
                #pragma unroll
                for (int d = 16; d > 0; d >>= 1)
                    s += __shfl_xor_sync(0xffffffffu, s, d);
                lc = __log2f(__ldg(&conf[b * FF + 4 * k + j]) / (s + 1e-10f));
            }

            // two independent weight chains from ONE shfl (u1 = u0 + 32)
            const float u0 = t_f - tbk;
            const float u1 = u0 + 32.0f;
            // out-of-window sub: arg < -450 -> ex2 == +0.0 (bitwise inert)
            const float w0 = ex2f(fmaf(u0 * c2, u0, lc));
            const float w1 = ex2f(fmaf(u1 * c2, u1, lc));
            unsigned long long ww0, ww1;
            asm("mov.b64 %0, {%1, %1};" : "=l"(ww0) : "f"(w0));
            asm("mov.b64 %0, {%1, %1};" : "=l"(ww1) : "f"(w1));

            const ulonglong2* row = reinterpret_cast<const ulonglong2*>(
                base + (4 * k + j) * PP);         // ONE 64B load stream, both subs
            #pragma unroll
            for (int q = 0; q < 4; ++q) {         // row[q] covers p = 4q..4q+3
                ulonglong2 v = __ldg(&row[q]);    // LDG.128 broadcast, L1-warm
                asm("fma.rn.f32x2 %0, %1, %2, %0;"
                    : "+l"(acc0[2 * q])     : "l"(ww0), "l"(v.x));
                asm("fma.rn.f32x2 %0, %1, %2, %0;"
                    : "+l"(acc0[2 * q + 1]) : "l"(ww0), "l"(v.y));
                asm("fma.rn.f32x2 %0, %1, %2, %0;"
                    : "+l"(acc1[2 * q])     : "l"(ww1), "l"(v.x));
                asm("fma.rn.f32x2 %0, %1, %2, %0;"
                    : "+l"(acc1[2 * q + 1]) : "l"(ww1), "l"(v.y));
            }
        }
    }

    // ---- stores: both sub-tiles, lanes span contiguous t (coalesced) ----
    // acc[j] holds p = 2j (lo) and 2j+1 (hi), matching row[q].x/.y -> acc[2q]/[2q+1].
    float* op = out + (size_t)(b * PP + p0) * TT + t0 + lane;
    #pragma unroll
    for (int j = 0; j < 8; ++j) {
        float lo0, hi0, lo1, hi1;
        asm("mov.b64 {%0, %1}, %2;" : "=f"(lo0), "=f"(hi0) : "l"(acc0[j]));
        asm("mov.b64 {%0, %1}, %2;" : "=f"(lo1), "=f"(hi1) : "l"(acc1[j]));
        op[(size_t)(2 * j)     * TT]      = lo0;
        op[(size_t)(2 * j + 1) * TT]      = hi0;
        op[(size_t)(2 * j)     * TT + 32] = lo1;
        op[(size_t)(2 * j + 1) * TT + 32] = hi1;
    }
}

extern "C" void kernel_launch(void* const* d_in, const int* in_sizes, int n_in,
                              void* d_out, int out_size)
{
    const float* pe = (const float*)d_in[0];           // flashes_pe [B,F,P]
    const float* tm = (const float*)d_in[1];           // flashes_time [B,F,1]
    const float* cf = (const float*)d_in[2];           // flashes_confidence [B,F,1]
    const float* sg = (n_in >= 4) ? (const float*)d_in[n_in - 1] : nullptr;  // sigma last

    dim3 grid(TT / 256, PP / 16, BB);                  // 8 x 16 x 8 = 1024 blocks
    flash_reco_kernel<<<grid, 128>>>(pe, tm, cf, sg, (float*)d_out);
}

// round 17
// speedup vs baseline: 1.0250x; 1.0250x over previous
#include <cuda_runtime.h>
#include <cuda_bf16.h>

#define BB 8
#define FF 128
#define PP 256
#define TT 2048

__device__ __forceinline__ float ex2f(float x) {
    float r;
    asm("ex2.approx.f32 %0, %1;" : "=f"(r) : "f"(x));
    return r;
}

// warp-autonomous: warp owns 64 ticks x 16 pe-channels as TWO tick-adjacent
// sub-lattices (lane covers t0+2*lane and t0+2*lane+1) fused in one flash
// loop: one shfl + one 64B LDG stream per flash, two independent ex2/FMA
// chains (ILP-2), and float2-vectorized stores. No smem, no barriers.
__global__ __launch_bounds__(128, 7)
void flash_reco_kernel(const float* __restrict__ pe,     // [B,F,P]
                       const float* __restrict__ ftime,  // [B,F]
                       const float* __restrict__ conf,   // [B,F]
                       const float* __restrict__ sigma_ptr,
                       float* __restrict__ out)          // [B,P,T]
{
    const int lane = threadIdx.x & 31;
    const int warp = threadIdx.x >> 5;
    const int b    = blockIdx.z;
    const int p0   = blockIdx.y * 16;                    // warp's 16 p
    const int t0   = blockIdx.x * 256 + warp * 64;       // warp's 64 ticks

    const float* __restrict__ base = pe + (size_t)(b * FF) * PP + p0;

    // cooperative prefetch: warm all 128 rows' 64B segment at this p0
    asm volatile("prefetch.global.L1 [%0];"
                 :: "l"(base + (warp * 32 + lane) * PP));

    const float sigma = sigma_ptr ? __ldg(sigma_ptr) : 1.0f;
    const float inv_s = 1.0f / sigma;
    const float W     = 6.0f * sigma;             // exp(-18) ~ 1.5e-8: negligible
    // interior normalizer: sigma*sqrt(2*pi); theta correction < 2.7e-9 @ sigma>=0.9
    const float inv_anorm = 1.0f / (sigma * 2.5066282746310002f + 1e-10f);
    const bool  analytic_ok = (sigma >= 0.9f);
    const float c2 = -0.72134752044448170f * inv_s * inv_s;  // -log2(e)/2 / s^2

    // ---- prefix: lane owns f = 4*lane+j; tb and lc = log2(conf/anorm) ----
    float4 tb4 = __ldg(reinterpret_cast<const float4*>(ftime + b * FF) + lane);
    float4 cf4 = __ldg(reinterpret_cast<const float4*>(conf  + b * FF) + lane);
    float tbs[4], lcs[4];
    tbs[0] = fminf(fmaxf(tb4.x * (float)TT, 0.0f), (float)(TT - 1));
    tbs[1] = fminf(fmaxf(tb4.y * (float)TT, 0.0f), (float)(TT - 1));
    tbs[2] = fminf(fmaxf(tb4.z * (float)TT, 0.0f), (float)(TT - 1));
    tbs[3] = fminf(fmaxf(tb4.w * (float)TT, 0.0f), (float)(TT - 1));
    lcs[0] = __log2f(cf4.x * inv_anorm);          // conf>=0: log2(0)=-inf -> w=0 ok
    lcs[1] = __log2f(cf4.y * inv_anorm);
    lcs[2] = __log2f(cf4.z * inv_anorm);
    lcs[3] = __log2f(cf4.w * inv_anorm);

    const float t_f = (float)(t0 + 2 * lane);            // even tick; odd = +1
    const float wlo = (float)t0 - W;                     // union window (64 ticks)
    const float whi = (float)(t0 + 63) + W;
    const float elo = W, ehi = (float)(TT - 1) - W;

    unsigned long long acc0[8], acc1[8];                 // even-t / odd-t lattices
    #pragma unroll
    for (int j = 0; j < 8; ++j) { acc0[j] = 0ull; acc1[j] = 0ull; }

    #pragma unroll
    for (int j = 0; j < 4; ++j) {
        unsigned mask =
            __ballot_sync(0xffffffffu, tbs[j] >= wlo && tbs[j] <= whi);
        while (mask) {                            // ascending f: deterministic
            const int k = __ffs(mask) - 1;
            mask &= mask - 1;
            const float tbk = __shfl_sync(0xffffffffu, tbs[j], k);
            float lc = __shfl_sync(0xffffffffu, lcs[j], k);

            if (!(analytic_ok && tbk >= elo && tbk <= ehi)) {  // rare, uniform
                const int lo = max(0, (int)ceilf(tbk - W));
                const int hi = min(TT - 1, (int)floorf(tbk + W));
                float s = 0.0f;
                for (int t = lo + lane; t <= hi; t += 32) {
                    const float zz = ((float)t - tbk) * inv_s;
                    s += __expf(-0.5f * zz * zz);
                }
                #pragma unroll
                for (int d = 16; d > 0; d >>= 1)
                    s += __shfl_xor_sync(0xffffffffu, s, d);
                lc = __log2f(__ldg(&conf[b * FF + 4 * k + j]) / (s + 1e-10f));
            }

            // two independent weight chains from ONE shfl (u1 = u0 + 1)
            const float u0 = t_f - tbk;
            const float u1 = u0 + 1.0f;
            const float w0 = ex2f(fmaf(u0 * c2, u0, lc));
            const float w1 = ex2f(fmaf(u1 * c2, u1, lc));
            unsigned long long ww0, ww1;
            asm("mov.b64 %0, {%1, %1};" : "=l"(ww0) : "f"(w0));
            asm("mov.b64 %0, {%1, %1};" : "=l"(ww1) : "f"(w1));

            const ulonglong2* row = reinterpret_cast<const ulonglong2*>(
                base + (4 * k + j) * PP);         // ONE 64B load stream, both subs
            #pragma unroll
            for (int q = 0; q < 4; ++q) {         // row[q] covers p = 4q..4q+3
                ulonglong2 v = __ldg(&row[q]);    // LDG.128 broadcast, L1-warm
                asm("fma.rn.f32x2 %0, %1, %2, %0;"
                    : "+l"(acc0[2 * q])     : "l"(ww0), "l"(v.x));
                asm("fma.rn.f32x2 %0, %1, %2, %0;"
                    : "+l"(acc0[2 * q + 1]) : "l"(ww0), "l"(v.y));
                asm("fma.rn.f32x2 %0, %1, %2, %0;"
                    : "+l"(acc1[2 * q])     : "l"(ww1), "l"(v.x));
                asm("fma.rn.f32x2 %0, %1, %2, %0;"
                    : "+l"(acc1[2 * q + 1]) : "l"(ww1), "l"(v.y));
            }
        }
    }

    // ---- stores: float2 per (p, tick-pair) -> 16 STG.64, coalesced ----
    // acc0[j] holds (p=2j lo, p=2j+1 hi) at even tick; acc1[j] same at odd tick.
    float* op = out + (size_t)(b * PP + p0) * TT + t0 + 2 * lane;  // 8B aligned
    #pragma unroll
    for (int j = 0; j < 8; ++j) {
        float lo0, hi0, lo1, hi1;
        asm("mov.b64 {%0, %1}, %2;" : "=f"(lo0), "=f"(hi0) : "l"(acc0[j]));
        asm("mov.b64 {%0, %1}, %2;" : "=f"(lo1), "=f"(hi1) : "l"(acc1[j]));
        *reinterpret_cast<float2*>(op + (size_t)(2 * j)     * TT) =
            make_float2(lo0, lo1);               // p=2j:   ticks t, t+1
        *reinterpret_cast<float2*>(op + (size_t)(2 * j + 1) * TT) =
            make_float2(hi0, hi1);               // p=2j+1: ticks t, t+1
    }
}

extern "C" void kernel_launch(void* const* d_in, const int* in_sizes, int n_in,
                              void* d_out, int out_size)
{
    const float* pe = (const float*)d_in[0];           // flashes_pe [B,F,P]
    const float* tm = (const float*)d_in[1];           // flashes_time [B,F,1]
    const float* cf = (const float*)d_in[2];           // flashes_confidence [B,F,1]
    const float* sg = (n_in >= 4) ? (const float*)d_in[n_in - 1] : nullptr;  // sigma last

    dim3 grid(TT / 256, PP / 16, BB);                  // 8 x 16 x 8 = 1024 blocks
    flash_reco_kernel<<<grid, 128>>>(pe, tm, cf, sg, (float*)d_out);
}